// round 8
// baseline (speedup 1.0000x reference)
#include <cuda_runtime.h>

// BaseTextureDiffusion: out[b,c,h,w] = sum_{k=0..48} weights[b,c,k,h,w] *
//                       latent_edgepadded[b,c, h+k/7-3, w+k%7-3]
// Shapes: latent (2,24,256,256) f32, weights (2,24,49,256,256) f32, R=7.
//
// HBM-bound on the 616MB read-once weights stream. R8 = R7 (90.5us) with a
// ROTATING weight buffer: consume wv[j] of row i, then immediately reload
// wv[j] with row i+1's value. Same one-row prefetch distance as the double
// buffer but 28 live weight regs instead of 56 -> __launch_bounds__(256,4)
// -> occ-4 (32 warps/SM) for smoother DRAM request supply.
// Keeps vectorized latent staging, hoisted row-0 loads, __ldcs/__stcs.

#define BB 2
#define CC 24
#define HH 256
#define WW 256
#define RR 7
#define PAD 3
#define HW (HH * WW)

#define TILE_ROWS 4                   // output rows per block
#define SROWS (TILE_ROWS + 2 * PAD)   // 10
#define SCOLS 264                     // latent cols -4..259
#define SC4   (SCOLS / 4)             // 66 float4 slots per tile row

__global__ __launch_bounds__(256, 4)
void texdiff_kernel(const float* __restrict__ latent,
                    const float* __restrict__ weights,
                    float* __restrict__ out)
{
    __shared__ float tile[SROWS][SCOLS];

    const int bc = blockIdx.z;                 // 0..47  (b*C + c)
    const int h0 = blockIdx.y * TILE_ROWS;     // first output row of tile
    const int x  = threadIdx.x;                // 0..63 : float4 lane over w
    const int y  = threadIdx.y;                // 0..3  : row within tile
    const int tid = y * 64 + x;                // 0..255
    const int w0  = 4 * x;

    const int h = h0 + y;
    const float* wbase = weights + (long)bc * (RR * RR) * HW + h * WW + w0;

    // Issue row-0 weight loads FIRST — independent of smem, so their
    // latency overlaps the tile staging below.
    float4 wv[RR];
    #pragma unroll
    for (int j = 0; j < RR; j++)
        wv[j] = __ldcs((const float4*)(wbase + (long)j * HW));

    const float* lat = latent + (long)bc * HW;

    // Stage latent tile with edge clamp, vectorized:
    // interior slots are aligned float4 copies; apron slots are clamped
    // scalar splats of column 0 / 255.
    #pragma unroll
    for (int idx = tid; idx < SROWS * SC4; idx += 256) {
        int r  = idx / SC4;
        int c4 = idx - r * SC4;
        int gh = h0 + r - PAD;
        gh = gh < 0 ? 0 : (gh > HH - 1 ? HH - 1 : gh);
        const float* lrow = lat + gh * WW;
        float4* dst = (float4*)&tile[r][c4 * 4];
        if (c4 == 0) {
            float v = lrow[0];
            *dst = make_float4(v, v, v, v);
        } else if (c4 == SC4 - 1) {
            float v = lrow[WW - 1];
            *dst = make_float4(v, v, v, v);
        } else {
            *dst = *(const float4*)(lrow + (c4 - 1) * 4);
        }
    }
    __syncthreads();

    float4 acc = make_float4(0.f, 0.f, 0.f, 0.f);

    #pragma unroll
    for (int i = 0; i < RR; i++) {
        // 12 consecutive latent values covering cols w0-3 .. w0+8
        const float4* srow = (const float4*)&tile[y + i][w0];
        float4 a = srow[0];
        float4 b = srow[1];
        float4 c = srow[2];
        float r[12] = { a.x, a.y, a.z, a.w,
                        b.x, b.y, b.z, b.w,
                        c.x, c.y, c.z, c.w };

        #pragma unroll
        for (int j = 0; j < RR; j++) {
            // Consume a snapshot, then immediately rotate the slot to the
            // next row's load — keeps one-row prefetch distance with only
            // 7 live weight float4s.
            float4 wj = wv[j];
            if (i < RR - 1)
                wv[j] = __ldcs((const float4*)(wbase + (long)((i + 1) * RR + j) * HW));
            acc.x += wj.x * r[1 + j];
            acc.y += wj.y * r[2 + j];
            acc.z += wj.z * r[3 + j];
            acc.w += wj.w * r[4 + j];
        }
    }

    __stcs((float4*)(out + (long)bc * HW + h * WW + w0), acc);
}

extern "C" void kernel_launch(void* const* d_in, const int* in_sizes, int n_in,
                              void* d_out, int out_size)
{
    const float* latent  = (const float*)d_in[0];
    const float* weights = (const float*)d_in[1];
    // d_in[2] = window_size (int scalar, always 7 here)
    float* out = (float*)d_out;

    dim3 block(64, TILE_ROWS, 1);
    dim3 grid(1, HH / TILE_ROWS, BB * CC);
    texdiff_kernel<<<grid, block>>>(latent, weights, out);
}

// round 9
// speedup vs baseline: 1.0200x; 1.0200x over previous
#include <cuda_runtime.h>

// BaseTextureDiffusion: out[b,c,h,w] = sum_{k=0..48} weights[b,c,k,h,w] *
//                       latent_edgepadded[b,c, h+k/7-3, w+k%7-3]
// Shapes: latent (2,24,256,256) f32, weights (2,24,49,256,256) f32, R=7.
//
// HBM-bound on the 616MB read-once weights stream. R9 = R7 skeleton
// (90.5us: double-buffered batched 7-load bursts, occ-3, vectorized latent
// staging, __ldcs/__stcs) with DISTANCE-2 prefetch: rows 0 AND 1 both
// loaded before the staging loop (latency hidden under staging), and row
// i+2's burst issued after row i's FMAs. Removes the block-start bubble;
// steady-state burst structure unchanged. (R8's interleaved rotating
// buffer regressed — keep bursts batched.)

#define BB 2
#define CC 24
#define HH 256
#define WW 256
#define RR 7
#define PAD 3
#define HW (HH * WW)

#define TILE_ROWS 4                   // output rows per block
#define SROWS (TILE_ROWS + 2 * PAD)   // 10
#define SCOLS 264                     // latent cols -4..259
#define SC4   (SCOLS / 4)             // 66 float4 slots per tile row

__global__ __launch_bounds__(256, 3)
void texdiff_kernel(const float* __restrict__ latent,
                    const float* __restrict__ weights,
                    float* __restrict__ out)
{
    __shared__ float tile[SROWS][SCOLS];

    const int bc = blockIdx.z;                 // 0..47  (b*C + c)
    const int h0 = blockIdx.y * TILE_ROWS;     // first output row of tile
    const int x  = threadIdx.x;                // 0..63 : float4 lane over w
    const int y  = threadIdx.y;                // 0..3  : row within tile
    const int tid = y * 64 + x;                // 0..255
    const int w0  = 4 * x;

    const int h = h0 + y;
    const float* wbase = weights + (long)bc * (RR * RR) * HW + h * WW + w0;

    // Fill BOTH buffers (window rows 0 and 1) before staging — all 14
    // loads' latency rides under the latent tile staging below.
    float4 wv[2][RR];
    #pragma unroll
    for (int j = 0; j < RR; j++)
        wv[0][j] = __ldcs((const float4*)(wbase + (long)j * HW));
    #pragma unroll
    for (int j = 0; j < RR; j++)
        wv[1][j] = __ldcs((const float4*)(wbase + (long)(RR + j) * HW));

    const float* lat = latent + (long)bc * HW;

    // Stage latent tile with edge clamp, vectorized:
    // interior slots are aligned float4 copies; apron slots are clamped
    // scalar splats of column 0 / 255.
    #pragma unroll
    for (int idx = tid; idx < SROWS * SC4; idx += 256) {
        int r  = idx / SC4;
        int c4 = idx - r * SC4;
        int gh = h0 + r - PAD;
        gh = gh < 0 ? 0 : (gh > HH - 1 ? HH - 1 : gh);
        const float* lrow = lat + gh * WW;
        float4* dst = (float4*)&tile[r][c4 * 4];
        if (c4 == 0) {
            float v = lrow[0];
            *dst = make_float4(v, v, v, v);
        } else if (c4 == SC4 - 1) {
            float v = lrow[WW - 1];
            *dst = make_float4(v, v, v, v);
        } else {
            *dst = *(const float4*)(lrow + (c4 - 1) * 4);
        }
    }
    __syncthreads();

    float4 acc = make_float4(0.f, 0.f, 0.f, 0.f);

    #pragma unroll
    for (int i = 0; i < RR; i++) {
        const int cur = i & 1;

        // 12 consecutive latent values covering cols w0-3 .. w0+8
        const float4* srow = (const float4*)&tile[y + i][w0];
        float4 a = srow[0];
        float4 b = srow[1];
        float4 c = srow[2];
        float r[12] = { a.x, a.y, a.z, a.w,
                        b.x, b.y, b.z, b.w,
                        c.x, c.y, c.z, c.w };

        #pragma unroll
        for (int j = 0; j < RR; j++) {
            acc.x += wv[cur][j].x * r[1 + j];
            acc.y += wv[cur][j].y * r[2 + j];
            acc.z += wv[cur][j].z * r[3 + j];
            acc.w += wv[cur][j].w * r[4 + j];
        }

        // Refill the just-consumed buffer with row i+2 (distance-2).
        if (i < RR - 2) {
            #pragma unroll
            for (int j = 0; j < RR; j++)
                wv[cur][j] =
                    __ldcs((const float4*)(wbase + (long)((i + 2) * RR + j) * HW));
        }
    }

    __stcs((float4*)(out + (long)bc * HW + h * WW + w0), acc);
}

extern "C" void kernel_launch(void* const* d_in, const int* in_sizes, int n_in,
                              void* d_out, int out_size)
{
    const float* latent  = (const float*)d_in[0];
    const float* weights = (const float*)d_in[1];
    // d_in[2] = window_size (int scalar, always 7 here)
    float* out = (float*)d_out;

    dim3 block(64, TILE_ROWS, 1);
    dim3 grid(1, HH / TILE_ROWS, BB * CC);
    texdiff_kernel<<<grid, block>>>(latent, weights, out);
}

// round 10
// speedup vs baseline: 1.0476x; 1.0270x over previous
#include <cuda_runtime.h>

// BaseTextureDiffusion: out[b,c,h,w] = sum_{k=0..48} weights[b,c,k,h,w] *
//                       latent_edgepadded[b,c, h+k/7-3, w+k%7-3]
// Shapes: latent (2,24,256,256) f32, weights (2,24,49,256,256) f32, R=7.
//
// HBM-bound on the 616MB read-once weights stream. R10 merges the two
// proven schedule pieces:
//  - R9's startup: window rows 0 AND 1 prefetched before latent staging
//    (their latency rides under the staging loads).
//  - R7's steady-state ordering: row i+2's batched 7-load burst issues
//    BEFORE row i's FMAs, so bursts always lead the consume chain.
// Keeps: 4-row tiles / 3072 blocks, occ-3, vectorized latent staging,
// __ldcs weights / __stcs out. (R8 showed interleaved reloads regress;
// R3/R4 showed persistent grids and taller tiles regress.)

#define BB 2
#define CC 24
#define HH 256
#define WW 256
#define RR 7
#define PAD 3
#define HW (HH * WW)

#define TILE_ROWS 4                   // output rows per block
#define SROWS (TILE_ROWS + 2 * PAD)   // 10
#define SCOLS 264                     // latent cols -4..259
#define SC4   (SCOLS / 4)             // 66 float4 slots per tile row

__global__ __launch_bounds__(256, 3)
void texdiff_kernel(const float* __restrict__ latent,
                    const float* __restrict__ weights,
                    float* __restrict__ out)
{
    __shared__ float tile[SROWS][SCOLS];

    const int bc = blockIdx.z;                 // 0..47  (b*C + c)
    const int h0 = blockIdx.y * TILE_ROWS;     // first output row of tile
    const int x  = threadIdx.x;                // 0..63 : float4 lane over w
    const int y  = threadIdx.y;                // 0..3  : row within tile
    const int tid = y * 64 + x;                // 0..255
    const int w0  = 4 * x;

    const int h = h0 + y;
    const float* wbase = weights + (long)bc * (RR * RR) * HW + h * WW + w0;

    // Prefetch window rows 0 and 1 before staging — latency hidden under
    // the latent tile staging below.
    float4 wv[2][RR];
    #pragma unroll
    for (int j = 0; j < RR; j++)
        wv[0][j] = __ldcs((const float4*)(wbase + (long)j * HW));
    #pragma unroll
    for (int j = 0; j < RR; j++)
        wv[1][j] = __ldcs((const float4*)(wbase + (long)(RR + j) * HW));

    const float* lat = latent + (long)bc * HW;

    // Stage latent tile with edge clamp, vectorized:
    // interior slots are aligned float4 copies; apron slots are clamped
    // scalar splats of column 0 / 255.
    #pragma unroll
    for (int idx = tid; idx < SROWS * SC4; idx += 256) {
        int r  = idx / SC4;
        int c4 = idx - r * SC4;
        int gh = h0 + r - PAD;
        gh = gh < 0 ? 0 : (gh > HH - 1 ? HH - 1 : gh);
        const float* lrow = lat + gh * WW;
        float4* dst = (float4*)&tile[r][c4 * 4];
        if (c4 == 0) {
            float v = lrow[0];
            *dst = make_float4(v, v, v, v);
        } else if (c4 == SC4 - 1) {
            float v = lrow[WW - 1];
            *dst = make_float4(v, v, v, v);
        } else {
            *dst = *(const float4*)(lrow + (c4 - 1) * 4);
        }
    }
    __syncthreads();

    float4 acc = make_float4(0.f, 0.f, 0.f, 0.f);

    // wv[i&1] holds row i; row i+1 already in flight / resident.
    // Each iteration: stash row i's values, issue row i+2's burst into the
    // just-freed buffer slot, then FMA row i.
    #pragma unroll
    for (int i = 0; i < RR; i++) {
        const int cur = i & 1;

        // Snapshot row i's weights so the buffer slot can be reloaded now.
        float4 wr[RR];
        #pragma unroll
        for (int j = 0; j < RR; j++)
            wr[j] = wv[cur][j];

        // Issue row i+2's burst BEFORE the FMAs (loads lead consumes).
        if (i < RR - 2) {
            #pragma unroll
            for (int j = 0; j < RR; j++)
                wv[cur][j] =
                    __ldcs((const float4*)(wbase + (long)((i + 2) * RR + j) * HW));
        }

        // 12 consecutive latent values covering cols w0-3 .. w0+8
        const float4* srow = (const float4*)&tile[y + i][w0];
        float4 a = srow[0];
        float4 b = srow[1];
        float4 c = srow[2];
        float r[12] = { a.x, a.y, a.z, a.w,
                        b.x, b.y, b.z, b.w,
                        c.x, c.y, c.z, c.w };

        #pragma unroll
        for (int j = 0; j < RR; j++) {
            acc.x += wr[j].x * r[1 + j];
            acc.y += wr[j].y * r[2 + j];
            acc.z += wr[j].z * r[3 + j];
            acc.w += wr[j].w * r[4 + j];
        }
    }

    __stcs((float4*)(out + (long)bc * HW + h * WW + w0), acc);
}

extern "C" void kernel_launch(void* const* d_in, const int* in_sizes, int n_in,
                              void* d_out, int out_size)
{
    const float* latent  = (const float*)d_in[0];
    const float* weights = (const float*)d_in[1];
    // d_in[2] = window_size (int scalar, always 7 here)
    float* out = (float*)d_out;

    dim3 block(64, TILE_ROWS, 1);
    dim3 grid(1, HH / TILE_ROWS, BB * CC);
    texdiff_kernel<<<grid, block>>>(latent, weights, out);
}